// round 10
// baseline (speedup 1.0000x reference)
#include <cuda_runtime.h>
#include <cuda_fp16.h>
#include <mma.h>
#include <cstdint>

using namespace nvcuda;

// Fused 2-layer GCN (chain graph), wmma fp16 3-term split.
// R10 = R9 + warp-split phase overlap in layer 2:
//   warps 0-3: MMA2 with 32x32 tiles (A-red 2, B-red 2: frag bytes 192->128KB)
//   warps 4-7: stencil2 chunk production (concurrent, double-buffered)
// Rest identical to R9 (persistent dual-group, OUT_TILE=62, resident weights).

#define NTHREADS 512
#define OUT_TILE 62
#define XROWS    66
#define HROWS    64

#define LDA1  72
#define LDW1  136
#define LDW2  72
#define LDH   130
#define LDX   68
#define LDA2C 40
#define LDO   68

#define OFF_W1H 0
#define OFF_W1L 17408
#define OFF_W2H 34816
#define OFF_W2L 53248
#define OFF_BB1 71680
#define OFF_BB2 75776
#define OFF_ONES 77824
#define OFF_GRP  78336
#define G_A    0
#define G_SH   20480
#define G_SXS  53760
#define G_SDV  71712
#define GRP_BYTES 72288
#define SMEM_BYTES (OFF_GRP + 2 * GRP_BYTES)   // 222912

__device__ __align__(256) __half g_W1ph[64 * 136];
__device__ __align__(256) __half g_W1pl[64 * 136];
__device__ __align__(256) __half g_W2ph[128 * 72];
__device__ __align__(256) __half g_W2pl[128 * 72];
__device__ __align__(256) __half g_Bb1[16 * 128];
__device__ __align__(256) __half g_Bb2[16 * 64];

__device__ __forceinline__ void split_h(float v, __half& hi, __half& lo) {
    hi = __float2half_rn(v);
    lo = __float2half_rn(v - __half2float(hi));
}
__device__ __forceinline__ uint32_t smem_u32(const void* p) {
    uint32_t a;
    asm("{ .reg .u64 t; cvta.to.shared.u64 t, %1; cvt.u32.u64 %0, t; }"
        : "=r"(a) : "l"(p));
    return a;
}
#define CP16(dst, src, nbytes) \
    asm volatile("cp.async.cg.shared.global [%0], [%1], 16, %2;" \
                 :: "r"(dst), "l"(src), "r"((uint32_t)(nbytes)))
#define CP_COMMIT() asm volatile("cp.async.commit_group;")
#define CP_WAIT0()  asm volatile("cp.async.wait_group 0;")
#define GBAR() asm volatile("bar.sync %0, %1;" :: "r"(grp + 1), "r"(256) : "memory")

__global__ void gcn_prep(const float* __restrict__ W1,
                         const float* __restrict__ b1,
                         const float* __restrict__ W2,
                         const float* __restrict__ b2)
{
    int tid = blockIdx.x * blockDim.x + threadIdx.x;
    int nt = gridDim.x * blockDim.x;
    for (int e = tid; e < 64 * 136; e += nt) {
        int r = e / 136, c = e % 136;
        __half hi = __float2half_rn(0.f), lo = hi;
        if (c < 128) split_h(W1[r * 128 + c], hi, lo);
        g_W1ph[e] = hi; g_W1pl[e] = lo;
    }
    for (int e = tid; e < 128 * 72; e += nt) {
        int r = e / 72, c = e % 72;
        __half hi = __float2half_rn(0.f), lo = hi;
        if (c < 64) split_h(W2[r * 64 + c], hi, lo);
        g_W2ph[e] = hi; g_W2pl[e] = lo;
    }
    for (int e = tid; e < 16 * 128; e += nt) {
        int r = e >> 7, c = e & 127;
        __half hi, lo; split_h(b1[c], hi, lo);
        g_Bb1[e] = (r == 0) ? hi : (r == 1) ? lo : __float2half_rn(0.f);
    }
    for (int e = tid; e < 16 * 64; e += nt) {
        int r = e >> 6, c = e & 63;
        __half hi, lo; split_h(b2[c], hi, lo);
        g_Bb2[e] = (r == 0) ? hi : (r == 1) ? lo : __float2half_rn(0.f);
    }
}

__global__ __launch_bounds__(NTHREADS, 1)
void gcn_main(const float* __restrict__ x, float* __restrict__ out, int N)
{
    extern __shared__ char smem[];
    const uint32_t sb = smem_u32(smem);
    const int tid = threadIdx.x;
    const int grp = tid >> 8;
    const int gtid = tid & 255;
    const int gwid = gtid >> 5;

    // ---------- one-time: stage W / biases ----------
    for (int e = tid; e < 1088; e += NTHREADS)
        CP16(sb + OFF_W1H + e * 16, (const char*)g_W1ph + e * 16, 16);
    for (int e = tid; e < 1088; e += NTHREADS)
        CP16(sb + OFF_W1L + e * 16, (const char*)g_W1pl + e * 16, 16);
    for (int e = tid; e < 1152; e += NTHREADS)
        CP16(sb + OFF_W2H + e * 16, (const char*)g_W2ph + e * 16, 16);
    for (int e = tid; e < 1152; e += NTHREADS)
        CP16(sb + OFF_W2L + e * 16, (const char*)g_W2pl + e * 16, 16);
    for (int e = tid; e < 256; e += NTHREADS)
        CP16(sb + OFF_BB1 + e * 16, (const char*)g_Bb1 + e * 16, 16);
    for (int e = tid; e < 128; e += NTHREADS)
        CP16(sb + OFF_BB2 + e * 16, (const char*)g_Bb2 + e * 16, 16);
    if (tid < 256)
        ((__half*)(smem + OFF_ONES))[tid] =
            __float2half_rn(((tid & 15) < 2) ? 1.0f : 0.0f);

    __half* W1h = (__half*)(smem + OFF_W1H);
    __half* W1l = (__half*)(smem + OFF_W1L);
    __half* W2h = (__half*)(smem + OFF_W2H);
    __half* W2l = (__half*)(smem + OFF_W2L);
    __half* sBb1 = (__half*)(smem + OFF_BB1);
    __half* sBb2 = (__half*)(smem + OFF_BB2);
    __half* sOnes = (__half*)(smem + OFF_ONES);

    char* gbp = smem + OFF_GRP + grp * GRP_BYTES;
    const uint32_t gb = sb + OFF_GRP + grp * GRP_BYTES;
    __half* A1h = (__half*)(gbp + G_A);
    __half* A1l = (__half*)(gbp + G_A + 9216);
    float* sH   = (float*)(gbp + G_SH);
    float* sOut = (float*)(gbp + G_SH);
    float* sXs  = (float*)(gbp + G_SXS);

    const long long ntiles = ((long long)N + OUT_TILE - 1) / OUT_TILE;
    const long long stride = (long long)gridDim.x * 2;
    long long tile = (long long)blockIdx.x * 2 + grp;
    int p = 0;

    // ---------- prologue: first tile's x + dinv ----------
    if (tile < ntiles) {
        long long base = tile * OUT_TILE;
        for (int e = gtid; e < XROWS * 16; e += 256) {
            int t = e >> 4, q = e & 15;
            long long node = base - 2 + t;
            bool ok = (node >= 0 && node < (long long)N);
            const float* src = ok ? (x + node * 64 + q * 4) : x;
            CP16(gb + G_SXS + (uint32_t)(t * 272 + q * 16), src, ok ? 16 : 0);
        }
        if (gtid < 68) {
            long long node = base - 2 + gtid;
            float v = 0.0f;
            if (node >= 0 && node < (long long)N)
                v = (node == 0 || node == (long long)N - 1)
                    ? 0.70710678118654752f : 0.57735026918962576f;
            ((float*)(gbp + G_SDV))[gtid] = v;
        }
    }
    CP_COMMIT();
    CP_WAIT0();
    __syncthreads();

    // ---------- persistent tile loop ----------
    for (; tile < ntiles; tile += stride) {
        const long long base = tile * OUT_TILE;
        float* sdv = (float*)(gbp + G_SDV + p * 288);

        // ---- stencil1 (4 rows/task, all 8 warps) -> A1 [64][64] ----
        for (int e = gtid; e < 16 * 32; e += 256) {
            int j0 = (e >> 5) * 4, kp = (e & 31) * 2;
            float2 v[6];
            #pragma unroll
            for (int i = 0; i < 6; i++)
                v[i] = *(float2*)&sXs[(j0 + i) * LDX + kp];
            #pragma unroll
            for (int rr = 0; rr < 4; rr++) {
                int j = j0 + rr;
                float d0 = sdv[j], d1 = sdv[j + 1], d2 = sdv[j + 2];
                float ax = d1 * (d0 * v[rr].x + d1 * v[rr + 1].x + d2 * v[rr + 2].x);
                float ay = d1 * (d0 * v[rr].y + d1 * v[rr + 1].y + d2 * v[rr + 2].y);
                __half hx, lx, hy, ly;
                split_h(ax, hx, lx);
                split_h(ay, hy, ly);
                *(__half2*)&A1h[j * LDA1 + kp] = __halves2half2(hx, hy);
                *(__half2*)&A1l[j * LDA1 + kp] = __halves2half2(lx, ly);
            }
        }
        GBAR();

        // ---- prefetch next tile's x + dinv ----
        {
            long long nt2 = tile + stride;
            if (nt2 < ntiles) {
                long long nbase = nt2 * OUT_TILE;
                for (int e = gtid; e < XROWS * 16; e += 256) {
                    int t = e >> 4, q = e & 15;
                    long long node = nbase - 2 + t;
                    bool ok = (node >= 0 && node < (long long)N);
                    const float* src = ok ? (x + node * 64 + q * 4) : x;
                    CP16(gb + G_SXS + (uint32_t)(t * 272 + q * 16), src, ok ? 16 : 0);
                }
                if (gtid < 68) {
                    long long node = nbase - 2 + gtid;
                    float v = 0.0f;
                    if (node >= 0 && node < (long long)N)
                        v = (node == 0 || node == (long long)N - 1)
                            ? 0.70710678118654752f : 0.57735026918962576f;
                    ((float*)(gbp + G_SDV + (p ^ 1) * 288))[gtid] = v;
                }
            }
            CP_COMMIT();
        }

        // ---- MMA1 (all 8 warps, 4x2): sH[64][128] = relu(A1 @ W1 + b1) ----
        {
            const int cg = gwid & 3, rg = gwid >> 2;
            wmma::fragment<wmma::matrix_a, 16, 16, 16, __half, wmma::row_major> ah, al;
            wmma::fragment<wmma::matrix_b, 16, 16, 16, __half, wmma::row_major> bh[2], bl[2];
            wmma::fragment<wmma::accumulator, 16, 16, 16, float> acc[2][2];
            #pragma unroll
            for (int r = 0; r < 2; r++)
                #pragma unroll
                for (int c = 0; c < 2; c++) wmma::fill_fragment(acc[r][c], 0.0f);

            wmma::load_matrix_sync(ah, sOnes, 16);
            #pragma unroll
            for (int c = 0; c < 2; c++)
                wmma::load_matrix_sync(bh[c], sBb1 + (cg * 2 + c) * 16, 128);
            #pragma unroll
            for (int r = 0; r < 2; r++)
                #pragma unroll
                for (int c = 0; c < 2; c++)
                    wmma::mma_sync(acc[r][c], ah, bh[c], acc[r][c]);

            #pragma unroll
            for (int k = 0; k < 4; k++) {
                #pragma unroll
                for (int c = 0; c < 2; c++) {
                    wmma::load_matrix_sync(bh[c], W1h + (k * 16) * LDW1 + (cg * 2 + c) * 16, LDW1);
                    wmma::load_matrix_sync(bl[c], W1l + (k * 16) * LDW1 + (cg * 2 + c) * 16, LDW1);
                }
                #pragma unroll
                for (int r = 0; r < 2; r++) {
                    wmma::load_matrix_sync(ah, A1h + ((rg * 2 + r) * 16) * LDA1 + k * 16, LDA1);
                    wmma::load_matrix_sync(al, A1l + ((rg * 2 + r) * 16) * LDA1 + k * 16, LDA1);
                    #pragma unroll
                    for (int c = 0; c < 2; c++) {
                        wmma::mma_sync(acc[r][c], ah, bh[c], acc[r][c]);
                        wmma::mma_sync(acc[r][c], ah, bl[c], acc[r][c]);
                        wmma::mma_sync(acc[r][c], al, bh[c], acc[r][c]);
                    }
                }
            }
            #pragma unroll
            for (int r = 0; r < 2; r++)
                #pragma unroll
                for (int c = 0; c < 2; c++) {
                    #pragma unroll
                    for (int i = 0; i < acc[r][c].num_elements; i++)
                        acc[r][c].x[i] = fmaxf(acc[r][c].x[i], 0.0f);
                    wmma::store_matrix_sync(
                        sH + ((rg * 2 + r) * 16) * LDH + (cg * 2 + c) * 16,
                        acc[r][c], LDH, wmma::mem_row_major);
                }
        }
        GBAR();          // sH ready; A1 dead (A2 chunk buffers may overwrite)

        // ---- stencil2 chunk producer (warps 4-7; 128 threads, 2 iters) ----
        auto stencil2_chunk = [&](int c, int b) {
            __half* bufh = (__half*)(gbp + G_A + b * 10240);
            __half* bufl = (__half*)(gbp + G_A + b * 10240 + 5120);
            int kc = c * 32;
            int st = gtid - 128;                 // 0..127
            #pragma unroll
            for (int it = 0; it < 2; it++) {
                int task = st + it * 128;        // 0..255
                int r0 = (task >> 4) * 4, kp = (task & 15) * 2;
                float2 v[6];
                #pragma unroll
                for (int i = 0; i < 6; i++)
                    v[i] = (r0 + i <= 63) ? *(float2*)&sH[(r0 + i) * LDH + kc + kp]
                                          : make_float2(0.f, 0.f);
                #pragma unroll
                for (int rr = 0; rr < 4; rr++) {
                    int r = r0 + rr;
                    float zx = 0.f, zy = 0.f;
                    if (r <= 61) {
                        float d1 = sdv[r + 1], d2 = sdv[r + 2], d3 = sdv[r + 3];
                        zx = d2 * (d1 * v[rr].x + d2 * v[rr + 1].x + d3 * v[rr + 2].x);
                        zy = d2 * (d1 * v[rr].y + d2 * v[rr + 1].y + d3 * v[rr + 2].y);
                    }
                    __half hx, lx, hy, ly;
                    split_h(zx, hx, lx);
                    split_h(zy, hy, ly);
                    *(__half2*)&bufh[r * LDA2C + kp] = __halves2half2(hx, hy);
                    *(__half2*)&bufl[r * LDA2C + kp] = __halves2half2(lx, ly);
                }
            }
        };

        // ---- layer 2: warps 0-3 MMA2 (32x32 tiles) || warps 4-7 stencil2 ----
        wmma::fragment<wmma::accumulator, 16, 16, 16, float> acc2[2][2];
        const int rs = gwid >> 1, cs = gwid & 1;   // valid for gwid<4
        if (gwid < 4) {
            #pragma unroll
            for (int r = 0; r < 2; r++)
                #pragma unroll
                for (int c = 0; c < 2; c++) wmma::fill_fragment(acc2[r][c], 0.0f);
            wmma::fragment<wmma::matrix_a, 16, 16, 16, __half, wmma::row_major> aon;
            wmma::fragment<wmma::matrix_b, 16, 16, 16, __half, wmma::row_major> bb;
            wmma::load_matrix_sync(aon, sOnes, 16);
            #pragma unroll
            for (int c = 0; c < 2; c++) {
                wmma::load_matrix_sync(bb, sBb2 + (cs * 2 + c) * 16, 64);
                #pragma unroll
                for (int r = 0; r < 2; r++)
                    wmma::mma_sync(acc2[r][c], aon, bb, acc2[r][c]);
            }
        } else {
            stencil2_chunk(0, 0);
        }
        GBAR();

        #pragma unroll
        for (int c = 0; c < 4; c++) {
            if (gwid >= 4) {
                if (c < 3) stencil2_chunk(c + 1, (c + 1) & 1);
            } else {
                __half* bufh = (__half*)(gbp + G_A + (c & 1) * 10240);
                __half* bufl = (__half*)(gbp + G_A + (c & 1) * 10240 + 5120);
                wmma::fragment<wmma::matrix_a, 16, 16, 16, __half, wmma::row_major> ah, al;
                wmma::fragment<wmma::matrix_b, 16, 16, 16, __half, wmma::row_major> bh, bl;
                #pragma unroll
                for (int s = 0; s < 2; s++) {
                    #pragma unroll
                    for (int cc = 0; cc < 2; cc++) {
                        wmma::load_matrix_sync(bh, W2h + (c * 32 + s * 16) * LDW2 + (cs * 2 + cc) * 16, LDW2);
                        wmma::load_matrix_sync(bl, W2l + (c * 32 + s * 16) * LDW2 + (cs * 2 + cc) * 16, LDW2);
                        #pragma unroll
                        for (int r = 0; r < 2; r++) {
                            wmma::load_matrix_sync(ah, bufh + ((rs * 2 + r) * 16) * LDA2C + s * 16, LDA2C);
                            wmma::load_matrix_sync(al, bufl + ((rs * 2 + r) * 16) * LDA2C + s * 16, LDA2C);
                            wmma::mma_sync(acc2[r][cc], ah, bh, acc2[r][cc]);
                            wmma::mma_sync(acc2[r][cc], ah, bl, acc2[r][cc]);
                            wmma::mma_sync(acc2[r][cc], al, bh, acc2[r][cc]);
                        }
                    }
                }
            }
            if (c == 3) CP_WAIT0();      // next-tile x landed
            GBAR();
        }

        // ---- store: rows <48 direct; rows 48..61 staged (warps 2,3 slab) ----
        if (base + OUT_TILE <= (long long)N) {
            if (gwid < 4) {
                #pragma unroll
                for (int r = 0; r < 2; r++) {
                    int row0 = (rs * 2 + r) * 16;
                    #pragma unroll
                    for (int cc = 0; cc < 2; cc++) {
                        int col0 = (cs * 2 + cc) * 16;
                        if (row0 < 48)
                            wmma::store_matrix_sync(out + (base + row0) * 64 + col0,
                                                    acc2[r][cc], 64, wmma::mem_row_major);
                        else
                            wmma::store_matrix_sync(sOut + col0, acc2[r][cc], LDO,
                                                    wmma::mem_row_major);
                    }
                }
            }
            GBAR();
            for (int e = gtid; e < 14 * 16; e += 256) {
                int r = e >> 4, q = e & 15;
                *(float4*)(out + (base + 48 + r) * 64 + q * 4) =
                    *(float4*)&sOut[r * LDO + q * 4];
            }
        } else {
            if (gwid < 4) {
                #pragma unroll
                for (int r = 0; r < 2; r++)
                    #pragma unroll
                    for (int cc = 0; cc < 2; cc++)
                        wmma::store_matrix_sync(
                            sOut + ((rs * 2 + r) * 16) * LDO + (cs * 2 + cc) * 16,
                            acc2[r][cc], LDO, wmma::mem_row_major);
            }
            GBAR();
            for (int e = gtid; e < 62 * 16; e += 256) {
                int r = e >> 4, q = e & 15;
                long long node = base + r;
                if (node < (long long)N)
                    *(float4*)(out + node * 64 + q * 4) =
                        *(float4*)&sOut[r * LDO + q * 4];
            }
        }
        GBAR();     // sOut/sH reads done before next tile's MMA1 epilogue
        p ^= 1;
    }
}

extern "C" void kernel_launch(void* const* d_in, const int* in_sizes, int n_in,
                              void* d_out, int out_size)
{
    const float* x  = (const float*)d_in[0];
    const float* W1 = (const float*)d_in[2];
    const float* b1 = (const float*)d_in[3];
    const float* W2 = (const float*)d_in[4];
    const float* b2 = (const float*)d_in[5];
    float* out = (float*)d_out;

    int N = in_sizes[0] / 64;

    int dev = 0, sms = 148;
    cudaGetDevice(&dev);
    cudaDeviceGetAttribute(&sms, cudaDevAttrMultiProcessorCount, dev);

    gcn_prep<<<32, 256>>>(W1, b1, W2, b2);

    cudaFuncSetAttribute(gcn_main,
                         cudaFuncAttributeMaxDynamicSharedMemorySize,
                         SMEM_BYTES);
    gcn_main<<<sms, NTHREADS, SMEM_BYTES>>>(x, out, N);
}